// round 1
// baseline (speedup 1.0000x reference)
#include <cuda_runtime.h>
#include <math.h>

#define HID    1024
#define H3     3072
#define SEQ    512
#define VOCAB  32000
#define RGRID  128
#define RTHREADS 256

// ---------------- device scratch (static: no allocations allowed) ----------------
__device__ float g_X[2][SEQ][HID];       // embedded enc/dec inputs        (4 MB)
__device__ float g_GX[2][SEQ][H3];       // precomputed Wih@x + bih        (12.6 MB)
__device__ float g_dec_hs[SEQ][HID];     // decoder hidden states          (2 MB)
__device__ float g_h[2][HID];            // ping-pong hidden state
__device__ unsigned g_bar;               // grid barrier counter

// ---------------- init: must reset per replay (graph re-executes) ----------------
__global__ void init_kernel() {
    int tid = threadIdx.x;
    g_h[0][tid] = 0.f;
    g_h[1][tid] = 0.f;
    if (tid == 0) g_bar = 0u;
}

// ---------------- embedding gather for encoder + decoder (teacher forcing) -------
__global__ void gather_kernel(const int* __restrict__ inputs,
                              const int* __restrict__ targets,
                              const float* __restrict__ emb) {
    int b = blockIdx.x;          // 0..1023
    int phase = b >> 9;          // 0 = enc, 1 = dec
    int t = b & (SEQ - 1);
    int tok = phase ? (t == 0 ? 0 : targets[t - 1]) : inputs[t];
    const float4* src = (const float4*)(emb + (size_t)tok * HID);
    float4* dst = (float4*)(&g_X[phase][t][0]);
    dst[threadIdx.x] = src[threadIdx.x];   // 256 threads x float4 = 1024 floats
}

// ---------------- fp32 NT GEMM: C[M][N] = A[M][K] * B[N][K]^T + bias --------------
// mode 0: A=g_X[0], C=g_GX[0]   (enc gx precompute, N=3072)
// mode 1: A=g_X[1], C=g_GX[1]   (dec gx precompute, N=3072)
// mode 2: A=g_dec_hs, C=Cout    (projection, N=32000)
__global__ void __launch_bounds__(256, 2) gemm_nt_kernel(
    int mode, const float* __restrict__ B, const float* __restrict__ bias,
    float* __restrict__ Cout, int N)
{
    const int K = HID;
    const float* A = (mode == 2) ? &g_dec_hs[0][0] : &g_X[mode][0][0];
    float* C = (mode == 2) ? Cout : &g_GX[mode][0][0];

    __shared__ float As[16][128];
    __shared__ float Bs[16][128];
    int tid = threadIdx.x;
    int bm = blockIdx.y * 128;
    int bn = blockIdx.x * 128;
    int lrow = tid >> 2;            // 0..63
    int lcol = (tid & 3) << 2;      // 0,4,8,12
    int tx = tid & 15;              // n micro-tile
    int ty = tid >> 4;              // m micro-tile
    const float* Ab = A + (size_t)bm * K;
    const float* Bb = B + (size_t)bn * K;

    float acc[8][8];
#pragma unroll
    for (int i = 0; i < 8; ++i)
#pragma unroll
        for (int j = 0; j < 8; ++j) acc[i][j] = 0.f;

    for (int k0 = 0; k0 < K; k0 += 16) {
#pragma unroll
        for (int r = 0; r < 2; ++r) {
            int row = lrow + r * 64;
            float4 a = *(const float4*)(Ab + (size_t)row * K + k0 + lcol);
            As[lcol + 0][row] = a.x; As[lcol + 1][row] = a.y;
            As[lcol + 2][row] = a.z; As[lcol + 3][row] = a.w;
            float4 b = *(const float4*)(Bb + (size_t)row * K + k0 + lcol);
            Bs[lcol + 0][row] = b.x; Bs[lcol + 1][row] = b.y;
            Bs[lcol + 2][row] = b.z; Bs[lcol + 3][row] = b.w;
        }
        __syncthreads();
#pragma unroll
        for (int kk = 0; kk < 16; ++kk) {
            float av[8], bv[8];
            *(float4*)&av[0] = *(const float4*)&As[kk][ty * 8];
            *(float4*)&av[4] = *(const float4*)&As[kk][ty * 8 + 4];
            *(float4*)&bv[0] = *(const float4*)&Bs[kk][tx * 8];
            *(float4*)&bv[4] = *(const float4*)&Bs[kk][tx * 8 + 4];
#pragma unroll
            for (int i = 0; i < 8; ++i)
#pragma unroll
                for (int j = 0; j < 8; ++j)
                    acc[i][j] = fmaf(av[i], bv[j], acc[i][j]);
        }
        __syncthreads();
    }

#pragma unroll
    for (int i = 0; i < 8; ++i) {
        int row = bm + ty * 8 + i;
#pragma unroll
        for (int j4 = 0; j4 < 2; ++j4) {
            int col = bn + tx * 8 + j4 * 4;
            float4 o;
            o.x = acc[i][j4 * 4 + 0] + bias[col + 0];
            o.y = acc[i][j4 * 4 + 1] + bias[col + 1];
            o.z = acc[i][j4 * 4 + 2] + bias[col + 2];
            o.w = acc[i][j4 * 4 + 3] + bias[col + 3];
            *(float4*)(C + (size_t)row * N + col) = o;
        }
    }
}

// ---------------- persistent GRU recurrence (encoder then decoder) ----------------
// 128 CTAs x 256 threads. Warp w of CTA b owns h index i = b*8+w and keeps the
// three Whh rows (r,z,n) for i entirely in registers (96 floats/thread).
// h double-buffered in GMEM; one grid barrier per step.
__global__ void __launch_bounds__(RTHREADS, 1) recurrence_kernel(
    const float* __restrict__ enc_Whh, const float* __restrict__ enc_bhh,
    const float* __restrict__ dec_Whh, const float* __restrict__ dec_bhh)
{
    extern __shared__ float smem[];
    float* sh  = smem;            // HID floats: current h
    float* sgx = smem + HID;      // SEQ*24 floats: this CTA's gx slice

    int tid = threadIdx.x;
    int warp = tid >> 5, lane = tid & 31;
    int base = blockIdx.x * 8;
    int i = base + warp;

    unsigned gen = 0;
    int s = 0;                    // global step counter across phases

    float wr[32], wz[32], wn[32];

    for (int phase = 0; phase < 2; ++phase) {
        const float* Whh = phase ? dec_Whh : enc_Whh;
        const float* bhh = phase ? dec_bhh : enc_bhh;
        const float* gxp = &g_GX[phase][0][0];

        // --- load this warp's 3 Whh rows into registers (coalesced float4) ---
        {
            const float* w0 = Whh + (size_t)i * HID;
            const float* w1 = Whh + (size_t)(HID + i) * HID;
            const float* w2 = Whh + (size_t)(2 * HID + i) * HID;
#pragma unroll
            for (int k = 0; k < 8; ++k) {
                int c = 4 * lane + 128 * k;
                float4 a = *(const float4*)(w0 + c);
                wr[4*k+0] = a.x; wr[4*k+1] = a.y; wr[4*k+2] = a.z; wr[4*k+3] = a.w;
                float4 b = *(const float4*)(w1 + c);
                wz[4*k+0] = b.x; wz[4*k+1] = b.y; wz[4*k+2] = b.z; wz[4*k+3] = b.w;
                float4 d = *(const float4*)(w2 + c);
                wn[4*k+0] = d.x; wn[4*k+1] = d.y; wn[4*k+2] = d.z; wn[4*k+3] = d.w;
            }
        }
        float br = bhh[i], bz = bhh[HID + i], bn = bhh[2 * HID + i];

        // --- stage this CTA's gx slice (3 gates x 8 outputs x 512 steps) in smem ---
        __syncthreads();
        for (int idx = tid; idx < SEQ * 24; idx += RTHREADS) {
            int t = idx / 24;
            int rr = idx - t * 24;
            int w = rr / 3, g = rr - 3 * w;
            sgx[idx] = gxp[(size_t)t * H3 + g * HID + base + w];
        }
        __syncthreads();

        for (int t = 0; t < SEQ; ++t, ++s) {
            int rb = s & 1, wb = rb ^ 1;
            // broadcast h into smem (L2 read, bypass stale L1)
            ((float4*)sh)[tid] = __ldcg(((const float4*)&g_h[rb][0]) + tid);
            __syncthreads();

            float ar = 0.f, az = 0.f, an = 0.f;
            const float4* shv = (const float4*)sh;
#pragma unroll
            for (int k = 0; k < 8; ++k) {
                float4 h4 = shv[lane + 32 * k];
                ar = fmaf(wr[4*k+0], h4.x, ar); ar = fmaf(wr[4*k+1], h4.y, ar);
                ar = fmaf(wr[4*k+2], h4.z, ar); ar = fmaf(wr[4*k+3], h4.w, ar);
                az = fmaf(wz[4*k+0], h4.x, az); az = fmaf(wz[4*k+1], h4.y, az);
                az = fmaf(wz[4*k+2], h4.z, az); az = fmaf(wz[4*k+3], h4.w, az);
                an = fmaf(wn[4*k+0], h4.x, an); an = fmaf(wn[4*k+1], h4.y, an);
                an = fmaf(wn[4*k+2], h4.z, an); an = fmaf(wn[4*k+3], h4.w, an);
            }
#pragma unroll
            for (int off = 16; off > 0; off >>= 1) {
                ar += __shfl_xor_sync(0xffffffffu, ar, off);
                az += __shfl_xor_sync(0xffffffffu, az, off);
                an += __shfl_xor_sync(0xffffffffu, an, off);
            }
            if (lane == 0) {
                const float* gx3 = &sgx[t * 24 + warp * 3];
                float r = 1.f / (1.f + expf(-(gx3[0] + ar + br)));
                float z = 1.f / (1.f + expf(-(gx3[1] + az + bz)));
                float n = tanhf(gx3[2] + r * (an + bn));
                float hnew = (1.f - z) * n + z * sh[i];
                g_h[wb][i] = hnew;
                if (phase) g_dec_hs[t][i] = hnew;
            }
            __syncthreads();
            // grid barrier: release own writes, wait for all 128 CTAs
            if (tid == 0) {
                __threadfence();
                atomicAdd(&g_bar, 1u);
                gen += RGRID;
                while (atomicAdd(&g_bar, 0u) < gen) { }
                __threadfence();
            }
            __syncthreads();
        }
    }
}

// ---------------- launch ----------------
extern "C" void kernel_launch(void* const* d_in, const int* in_sizes, int n_in,
                              void* d_out, int out_size) {
    const int*   inputs  = (const int*)d_in[0];
    const int*   targets = (const int*)d_in[1];
    const float* emb     = (const float*)d_in[2];
    const float* enc_Wih = (const float*)d_in[3];
    const float* enc_Whh = (const float*)d_in[4];
    const float* enc_bih = (const float*)d_in[5];
    const float* enc_bhh = (const float*)d_in[6];
    const float* dec_Wih = (const float*)d_in[7];
    const float* dec_Whh = (const float*)d_in[8];
    const float* dec_bih = (const float*)d_in[9];
    const float* dec_bhh = (const float*)d_in[10];
    const float* proj_W  = (const float*)d_in[11];
    const float* proj_b  = (const float*)d_in[12];
    float* out = (float*)d_out;

    const int rec_smem = (HID + SEQ * 24) * 4;   // 53,248 B
    cudaFuncSetAttribute(recurrence_kernel,
                         cudaFuncAttributeMaxDynamicSharedMemorySize, rec_smem);

    init_kernel<<<1, 1024>>>();
    gather_kernel<<<2 * SEQ, 256>>>(inputs, targets, emb);

    dim3 g_gx(H3 / 128, SEQ / 128);          // 24 x 4
    gemm_nt_kernel<<<g_gx, 256>>>(0, enc_Wih, enc_bih, nullptr, H3);
    gemm_nt_kernel<<<g_gx, 256>>>(1, dec_Wih, dec_bih, nullptr, H3);

    recurrence_kernel<<<RGRID, RTHREADS, rec_smem>>>(enc_Whh, enc_bhh,
                                                     dec_Whh, dec_bhh);

    dim3 g_proj(VOCAB / 128, SEQ / 128);     // 250 x 4
    gemm_nt_kernel<<<g_proj, 256>>>(2, proj_W, proj_b, out, VOCAB);
}

// round 2
// speedup vs baseline: 1.3142x; 1.3142x over previous
#include <cuda_runtime.h>
#include <math.h>

#define HID    1024
#define H3     3072
#define SEQ    512
#define VOCAB  32000
#define RGRID  128
#define RTHREADS 256

// ---------------- device scratch (static: no allocations allowed) ----------------
__device__ float g_X[2][SEQ][HID];                 // embedded enc/dec inputs
__device__ float g_GX[2][SEQ][H3];                 // precomputed Wih@x + bih
__device__ float g_dec_hs[SEQ][HID];               // decoder hidden states
__device__ unsigned long long g_ring[3][HID];      // (tag<<32)|float bits, depth-3 ring

// ---------------- packed f32x2 helpers (FFMA2: 2x fp32 rate, PTX-only) -----------
__device__ __forceinline__ unsigned long long pk2(float x, float y) {
    unsigned long long r;
    asm("mov.b64 %0,{%1,%2};" : "=l"(r) : "f"(x), "f"(y));
    return r;
}
__device__ __forceinline__ unsigned long long f2fma(unsigned long long a,
                                                    unsigned long long b,
                                                    unsigned long long c) {
    unsigned long long d;
    asm("fma.rn.f32x2 %0,%1,%2,%3;" : "=l"(d) : "l"(a), "l"(b), "l"(c));
    return d;
}
__device__ __forceinline__ float2 up2(unsigned long long v) {
    float2 f;
    asm("mov.b64 {%0,%1},%2;" : "=f"(f.x), "=f"(f.y) : "l"(v));
    return f;
}
// relaxed gpu-scope 8B atomics (single-word value+tag publication, L2 visible)
__device__ __forceinline__ unsigned long long ldrx(const unsigned long long* p) {
    unsigned long long v;
    asm volatile("ld.global.relaxed.gpu.b64 %0,[%1];" : "=l"(v) : "l"(p));
    return v;
}
__device__ __forceinline__ void strx(unsigned long long* p, unsigned long long v) {
    asm volatile("st.global.relaxed.gpu.b64 [%0],%1;" :: "l"(p), "l"(v) : "memory");
}

// ---------------- init: must reset per replay (graph re-executes) ----------------
__global__ void init_kernel() {
    int tid = threadIdx.x;                       // 1024 threads
    g_ring[0][tid] = 0ULL;                       // tag 0, value 0.0f
    g_ring[1][tid] = 0xFFFFFFFF00000000ULL;      // sentinel tag
    g_ring[2][tid] = 0xFFFFFFFF00000000ULL;
}

// ---------------- embedding gather (encoder + teacher-forced decoder) ------------
__global__ void gather_kernel(const int* __restrict__ inputs,
                              const int* __restrict__ targets,
                              const float* __restrict__ emb) {
    int b = blockIdx.x;          // 0..1023
    int phase = b >> 9;
    int t = b & (SEQ - 1);
    int tok = phase ? (t == 0 ? 0 : targets[t - 1]) : inputs[t];
    const float4* src = (const float4*)(emb + (size_t)tok * HID);
    float4* dst = (float4*)(&g_X[phase][t][0]);
    dst[threadIdx.x] = src[threadIdx.x];
}

// ---------------- fp32 NT GEMM, FFMA2 + double-buffered smem ---------------------
// C[M][N] = A[M][K] * B[N][K]^T + bias ; K = 1024, tiles 128x128x16, 8x8/thread
// mode 0/1: A=g_X[mode], C=g_GX[mode] (N=3072). mode 2: A=g_dec_hs, C=Cout (N=32000).
__global__ void __launch_bounds__(256, 2) gemm_nt_kernel(
    int mode, const float* __restrict__ B, const float* __restrict__ bias,
    float* __restrict__ Cout, int N)
{
    const int K = HID;
    const float* A = (mode == 2) ? &g_dec_hs[0][0] : &g_X[mode][0][0];
    float* C = (mode == 2) ? Cout : &g_GX[mode][0][0];

    __shared__ float As[2][16][132];
    __shared__ float Bs[2][16][132];

    int tid = threadIdx.x;
    int bm = blockIdx.y * 128;
    int bn = blockIdx.x * 128;
    int lrow = tid >> 2;            // 0..63
    int lcol = (tid & 3) << 2;      // 0,4,8,12
    int tx = tid & 15;
    int ty = tid >> 4;
    const float* Ab = A + (size_t)bm * K;
    const float* Bb = B + (size_t)bn * K;

    unsigned long long acc2[8][4];
#pragma unroll
    for (int i = 0; i < 8; ++i)
#pragma unroll
        for (int j = 0; j < 4; ++j) acc2[i][j] = 0ULL;

    float4 pa[2], pb[2];
    // prologue: load tile 0
#pragma unroll
    for (int r = 0; r < 2; ++r) {
        int row = lrow + r * 64;
        pa[r] = *(const float4*)(Ab + (size_t)row * K + lcol);
        pb[r] = *(const float4*)(Bb + (size_t)row * K + lcol);
    }
#pragma unroll
    for (int r = 0; r < 2; ++r) {
        int row = lrow + r * 64;
        As[0][lcol + 0][row] = pa[r].x; As[0][lcol + 1][row] = pa[r].y;
        As[0][lcol + 2][row] = pa[r].z; As[0][lcol + 3][row] = pa[r].w;
        Bs[0][lcol + 0][row] = pb[r].x; Bs[0][lcol + 1][row] = pb[r].y;
        Bs[0][lcol + 2][row] = pb[r].z; Bs[0][lcol + 3][row] = pb[r].w;
    }
    __syncthreads();

    int cur = 0;
    for (int k0 = 0; k0 < K; k0 += 16) {
        bool more = (k0 + 16) < K;
        if (more) {
#pragma unroll
            for (int r = 0; r < 2; ++r) {
                int row = lrow + r * 64;
                pa[r] = *(const float4*)(Ab + (size_t)row * K + k0 + 16 + lcol);
                pb[r] = *(const float4*)(Bb + (size_t)row * K + k0 + 16 + lcol);
            }
        }
#pragma unroll
        for (int kk = 0; kk < 16; ++kk) {
            float4 av0 = *(const float4*)&As[cur][kk][ty * 8];
            float4 av1 = *(const float4*)&As[cur][kk][ty * 8 + 4];
            ulonglong2 bv0 = *(const ulonglong2*)&Bs[cur][kk][tx * 8];
            ulonglong2 bv1 = *(const ulonglong2*)&Bs[cur][kk][tx * 8 + 4];
            unsigned long long a2[8];
            a2[0] = pk2(av0.x, av0.x); a2[1] = pk2(av0.y, av0.y);
            a2[2] = pk2(av0.z, av0.z); a2[3] = pk2(av0.w, av0.w);
            a2[4] = pk2(av1.x, av1.x); a2[5] = pk2(av1.y, av1.y);
            a2[6] = pk2(av1.z, av1.z); a2[7] = pk2(av1.w, av1.w);
#pragma unroll
            for (int i = 0; i < 8; ++i) {
                acc2[i][0] = f2fma(a2[i], bv0.x, acc2[i][0]);
                acc2[i][1] = f2fma(a2[i], bv0.y, acc2[i][1]);
                acc2[i][2] = f2fma(a2[i], bv1.x, acc2[i][2]);
                acc2[i][3] = f2fma(a2[i], bv1.y, acc2[i][3]);
            }
        }
        if (more) {
            int alt = cur ^ 1;
#pragma unroll
            for (int r = 0; r < 2; ++r) {
                int row = lrow + r * 64;
                As[alt][lcol + 0][row] = pa[r].x; As[alt][lcol + 1][row] = pa[r].y;
                As[alt][lcol + 2][row] = pa[r].z; As[alt][lcol + 3][row] = pa[r].w;
                Bs[alt][lcol + 0][row] = pb[r].x; Bs[alt][lcol + 1][row] = pb[r].y;
                Bs[alt][lcol + 2][row] = pb[r].z; Bs[alt][lcol + 3][row] = pb[r].w;
            }
        }
        __syncthreads();
        cur ^= 1;
    }

#pragma unroll
    for (int i = 0; i < 8; ++i) {
        int row = bm + ty * 8 + i;
        float2 c0 = up2(acc2[i][0]), c1 = up2(acc2[i][1]);
        float2 c2 = up2(acc2[i][2]), c3 = up2(acc2[i][3]);
        int col = bn + tx * 8;
        float4 o0, o1;
        o0.x = c0.x + bias[col + 0]; o0.y = c0.y + bias[col + 1];
        o0.z = c1.x + bias[col + 2]; o0.w = c1.y + bias[col + 3];
        o1.x = c2.x + bias[col + 4]; o1.y = c2.y + bias[col + 5];
        o1.z = c3.x + bias[col + 6]; o1.w = c3.y + bias[col + 7];
        *(float4*)(C + (size_t)row * N + col) = o0;
        *(float4*)(C + (size_t)row * N + col + 4) = o1;
    }
}

// ---------------- persistent GRU recurrence, barrier-free ------------------------
// 128 CTAs x 256 threads. Warp w of CTA b owns h index i = b*8+w; 3 Whh rows live
// in registers as f32x2 pairs. h published as (tag|bits) words in a depth-3 ring;
// consumers poll the tags of the words they read (no grid barrier at all).
__global__ void __launch_bounds__(RTHREADS, 1) recurrence_kernel(
    const float* __restrict__ enc_Whh, const float* __restrict__ enc_bhh,
    const float* __restrict__ dec_Whh, const float* __restrict__ dec_bhh)
{
    extern __shared__ float smem[];
    float* sh  = smem;            // HID floats: current h
    float* sgx = smem + HID;      // SEQ*24 floats: this CTA's gx slice

    int tid = threadIdx.x;
    int warp = tid >> 5, lane = tid & 31;
    int base = blockIdx.x * 8;
    int i = base + warp;
    int s = 0;                    // global step across phases

    unsigned long long wr2[16], wz2[16], wn2[16];

    for (int phase = 0; phase < 2; ++phase) {
        const float* Whh = phase ? dec_Whh : enc_Whh;
        const float* bhh = phase ? dec_bhh : enc_bhh;
        const float* gxp = &g_GX[phase][0][0];

        {   // 3 Whh rows -> registers as adjacent-k pairs
            const float* w0 = Whh + (size_t)i * HID;
            const float* w1 = Whh + (size_t)(HID + i) * HID;
            const float* w2 = Whh + (size_t)(2 * HID + i) * HID;
#pragma unroll
            for (int k = 0; k < 8; ++k) {
                int c = 4 * lane + 128 * k;
                float4 a = *(const float4*)(w0 + c);
                wr2[2*k] = pk2(a.x, a.y); wr2[2*k+1] = pk2(a.z, a.w);
                float4 b = *(const float4*)(w1 + c);
                wz2[2*k] = pk2(b.x, b.y); wz2[2*k+1] = pk2(b.z, b.w);
                float4 d = *(const float4*)(w2 + c);
                wn2[2*k] = pk2(d.x, d.y); wn2[2*k+1] = pk2(d.z, d.w);
            }
        }
        float br = bhh[i], bz = bhh[HID + i], bnn = bhh[2 * HID + i];

        __syncthreads();
        for (int idx = tid; idx < SEQ * 24; idx += RTHREADS) {
            int t = idx / 24;
            int rr = idx - t * 24;
            int w = rr / 3, g = rr - 3 * w;
            sgx[idx] = gxp[(size_t)t * H3 + g * HID + base + w];
        }
        __syncthreads();

        for (int t = 0; t < SEQ; ++t, ++s) {
            // ---- wait for h_s: poll tags fused with the data read ----
            const unsigned long long* ring = g_ring[s % 3];
            unsigned exp = (unsigned)s;
            unsigned long long v0, v1, v2, v3;
            for (;;) {
                v0 = ldrx(ring + tid);
                v1 = ldrx(ring + tid + 256);
                v2 = ldrx(ring + tid + 512);
                v3 = ldrx(ring + tid + 768);
                bool ok = ((unsigned)(v0 >> 32) == exp) &&
                          ((unsigned)(v1 >> 32) == exp) &&
                          ((unsigned)(v2 >> 32) == exp) &&
                          ((unsigned)(v3 >> 32) == exp);
                if (__syncthreads_and(ok)) break;
            }
            sh[tid      ] = __uint_as_float((unsigned)v0);
            sh[tid + 256] = __uint_as_float((unsigned)v1);
            sh[tid + 512] = __uint_as_float((unsigned)v2);
            sh[tid + 768] = __uint_as_float((unsigned)v3);
            __syncthreads();

            // ---- dot products (FFMA2 pairs) ----
            unsigned long long ar2 = 0ULL, az2 = 0ULL, an2 = 0ULL;
            const ulonglong2* shv = (const ulonglong2*)sh;
#pragma unroll
            for (int k = 0; k < 8; ++k) {
                ulonglong2 hv = shv[lane + 32 * k];
                ar2 = f2fma(wr2[2*k], hv.x, ar2); ar2 = f2fma(wr2[2*k+1], hv.y, ar2);
                az2 = f2fma(wz2[2*k], hv.x, az2); az2 = f2fma(wz2[2*k+1], hv.y, az2);
                an2 = f2fma(wn2[2*k], hv.x, an2); an2 = f2fma(wn2[2*k+1], hv.y, an2);
            }
            float2 arf = up2(ar2), azf = up2(az2), anf = up2(an2);
            float ar = arf.x + arf.y, az = azf.x + azf.y, an = anf.x + anf.y;
#pragma unroll
            for (int off = 16; off > 0; off >>= 1) {
                ar += __shfl_xor_sync(0xffffffffu, ar, off);
                az += __shfl_xor_sync(0xffffffffu, az, off);
                an += __shfl_xor_sync(0xffffffffu, an, off);
            }
            if (lane == 0) {
                const float* gx3 = &sgx[t * 24 + warp * 3];
                float r = 1.f / (1.f + expf(-(gx3[0] + ar + br)));
                float z = 1.f / (1.f + expf(-(gx3[1] + az + bz)));
                float n = tanhf(gx3[2] + r * (an + bnn));
                float hnew = (1.f - z) * n + z * sh[i];
                if (phase) g_dec_hs[t][i] = hnew;
                unsigned long long pub =
                    ((unsigned long long)(unsigned)(s + 1) << 32) |
                    (unsigned long long)__float_as_uint(hnew);
                strx(&g_ring[(s + 1) % 3][i], pub);
            }
            // no block/grid barrier: next step's poll provides all ordering
        }
    }
}

// ---------------- launch ----------------
extern "C" void kernel_launch(void* const* d_in, const int* in_sizes, int n_in,
                              void* d_out, int out_size) {
    const int*   inputs  = (const int*)d_in[0];
    const int*   targets = (const int*)d_in[1];
    const float* emb     = (const float*)d_in[2];
    const float* enc_Wih = (const float*)d_in[3];
    const float* enc_Whh = (const float*)d_in[4];
    const float* enc_bih = (const float*)d_in[5];
    const float* enc_bhh = (const float*)d_in[6];
    const float* dec_Wih = (const float*)d_in[7];
    const float* dec_Whh = (const float*)d_in[8];
    const float* dec_bih = (const float*)d_in[9];
    const float* dec_bhh = (const float*)d_in[10];
    const float* proj_W  = (const float*)d_in[11];
    const float* proj_b  = (const float*)d_in[12];
    float* out = (float*)d_out;

    const int rec_smem = (HID + SEQ * 24) * 4;   // 53,248 B
    cudaFuncSetAttribute(recurrence_kernel,
                         cudaFuncAttributeMaxDynamicSharedMemorySize, rec_smem);

    init_kernel<<<1, 1024>>>();
    gather_kernel<<<2 * SEQ, 256>>>(inputs, targets, emb);

    dim3 g_gx(H3 / 128, SEQ / 128);          // 24 x 4
    gemm_nt_kernel<<<g_gx, 256>>>(0, enc_Wih, enc_bih, nullptr, H3);
    gemm_nt_kernel<<<g_gx, 256>>>(1, dec_Wih, dec_bih, nullptr, H3);

    recurrence_kernel<<<RGRID, RTHREADS, rec_smem>>>(enc_Whh, enc_bhh,
                                                     dec_Whh, dec_bhh);

    dim3 g_proj(VOCAB / 128, SEQ / 128);     // 250 x 4
    gemm_nt_kernel<<<g_proj, 256>>>(2, proj_W, proj_b, out, VOCAB);
}